// round 5
// baseline (speedup 1.0000x reference)
#include <cuda_runtime.h>
#include <math.h>

#define NN 100000
#define EE 1600000
#define MM (EE + NN)
#define DD 128

// ---------------- scratch (static device allocations; no runtime alloc) ----
__device__ int   g_deg[NN];
__device__ float g_sumw[NN];
__device__ float g_loopw[NN];
__device__ int   g_rowptr[NN + 1];
__device__ int   g_wp[NN];
__device__ int   g_bsum[128];
__device__ int   g_ssrc[MM];
__device__ float g_sew[MM];
__device__ float g_as[NN];
__device__ float g_ad[NN];
__device__ __align__(16) float g_H[(size_t)NN * DD];
__device__ __align__(16) float g_ACT[(size_t)NN * DD];
__device__ float g_ce[2];

// ---------------- preprocessing ----------------
__global__ void k_init() {
    int i = blockIdx.x * blockDim.x + threadIdx.x;
    if (i < NN) { g_deg[i] = 0; g_sumw[i] = 0.f; }
}

// edge_index is INT32 (JAX default x64-disabled: astype(int64) is a no-op)
__global__ void k_deg(const int* __restrict__ ei, const float* __restrict__ ew) {
    int i = blockIdx.x * blockDim.x + threadIdx.x;
    if (i < EE) {
        int d = ei[EE + i];
        atomicAdd(&g_deg[d], 1);
        atomicAdd(&g_sumw[d], ew[i]);
    }
}

__global__ void k_loopw() {
    int i = blockIdx.x * blockDim.x + threadIdx.x;
    if (i < NN) {
        int d = g_deg[i];
        g_loopw[i] = g_sumw[i] / (float)(d > 1 ? d : 1);
    }
}

__global__ void k_scan1() {
    __shared__ int s[1024];
    int i = blockIdx.x * 1024 + threadIdx.x;
    int v = (i < NN) ? g_deg[i] + 1 : 0;   // +1 self-loop
    s[threadIdx.x] = v;
    __syncthreads();
    for (int off = 1; off < 1024; off <<= 1) {
        int t = (threadIdx.x >= off) ? s[threadIdx.x - off] : 0;
        __syncthreads();
        s[threadIdx.x] += t;
        __syncthreads();
    }
    if (i < NN) g_rowptr[i] = s[threadIdx.x] - v;   // exclusive within block
    if (threadIdx.x == 1023) g_bsum[blockIdx.x] = s[1023];
}

__global__ void k_scan2(int nb) {
    if (blockIdx.x == 0 && threadIdx.x == 0) {
        int acc = 0;
        for (int b = 0; b < nb; b++) { int t = g_bsum[b]; g_bsum[b] = acc; acc += t; }
        g_rowptr[NN] = MM;
    }
}

__global__ void k_scan3() {
    int i = blockIdx.x * blockDim.x + threadIdx.x;
    if (i < NN) {
        int v = g_rowptr[i] + g_bsum[i >> 10];
        g_rowptr[i] = v;
        g_wp[i] = v;
    }
}

__global__ void k_scatter(const int* __restrict__ ei, const float* __restrict__ ew) {
    int i = blockIdx.x * blockDim.x + threadIdx.x;
    if (i < EE) {
        int s = ei[i];
        int d = ei[EE + i];
        int pos = atomicAdd(&g_wp[d], 1);
        g_ssrc[pos] = s;
        g_sew[pos] = ew[i];
    } else if (i < MM) {
        int n = i - EE;
        int pos = atomicAdd(&g_wp[n], 1);
        g_ssrc[pos] = n;
        g_sew[pos] = g_loopw[n];
    }
}

__global__ void k_ce(const float* __restrict__ lew, const float* __restrict__ ae) {
    int t = threadIdx.x;   // 128 threads
    float p0 = lew[t] * ae[t];
    float p1 = lew[DD + t] * ae[DD + t];
    for (int o = 16; o; o >>= 1) {
        p0 += __shfl_xor_sync(0xffffffffu, p0, o);
        p1 += __shfl_xor_sync(0xffffffffu, p1, o);
    }
    __shared__ float s0[4], s1[4];
    if ((t & 31) == 0) { s0[t >> 5] = p0; s1[t >> 5] = p1; }
    __syncthreads();
    if (t == 0) {
        g_ce[0] = s0[0] + s0[1] + s0[2] + s0[3];
        g_ce[1] = s1[0] + s1[1] + s1[2] + s1[3];
    }
}

// ---------------- GEMM: 64x128 tile / block, k chunked by 32, static smem ----
// 256 threads: tx in [0,16) covers 8 cols, ty in [0,16) covers 4 rows.
// SRC=0: read Xin param; SRC=1: read g_ACT. Always writes g_H.
template<int SRC>
__global__ void k_gemm(const float* __restrict__ Xin, const float* __restrict__ Wg) {
    __shared__ __align__(16) float sW[32][DD];    // 16 KB
    __shared__ float sX[64][36];                  // 9.2 KB (pad 36 -> conflict-free)
    const float* __restrict__ X = (SRC == 0) ? Xin : (const float*)g_ACT;

    int tid = threadIdx.x;
    int row0 = blockIdx.x * 64;
    int tx = tid & 15, ty = tid >> 4;
    int ty4 = ty * 4, c0 = tx * 8;

    float acc[4][8];
#pragma unroll
    for (int i = 0; i < 4; i++)
#pragma unroll
        for (int j = 0; j < 8; j++) acc[i][j] = 0.f;

    for (int kc = 0; kc < DD; kc += 32) {
        // load W chunk [32][128]: 1024 float4, 4 per thread
#pragma unroll
        for (int t = 0; t < 4; t++) {
            int idx = tid + t * 256;
            int r = idx >> 5, c4 = idx & 31;
            float4 v = ((const float4*)Wg)[(kc + r) * 32 + c4];
            *(float4*)&sW[r][c4 * 4] = v;
        }
        // load X chunk [64][32]: 512 float4, 2 per thread (scalar stores, pad 36)
#pragma unroll
        for (int t = 0; t < 2; t++) {
            int idx = tid + t * 256;
            int r = idx >> 3, c4 = idx & 7;
            float4 v = make_float4(0.f, 0.f, 0.f, 0.f);
            if (row0 + r < NN) v = ((const float4*)X)[(row0 + r) * 32 + (kc >> 2) + c4];
            sX[r][c4 * 4 + 0] = v.x;
            sX[r][c4 * 4 + 1] = v.y;
            sX[r][c4 * 4 + 2] = v.z;
            sX[r][c4 * 4 + 3] = v.w;
        }
        __syncthreads();

#pragma unroll 4
        for (int kk = 0; kk < 32; kk++) {
            float4 wa = *(const float4*)&sW[kk][c0];
            float4 wb = *(const float4*)&sW[kk][c0 + 4];
            float wv[8] = {wa.x, wa.y, wa.z, wa.w, wb.x, wb.y, wb.z, wb.w};
            float xv[4];
#pragma unroll
            for (int i = 0; i < 4; i++) xv[i] = sX[ty4 + i][kk];
#pragma unroll
            for (int i = 0; i < 4; i++)
#pragma unroll
                for (int j = 0; j < 8; j++)
                    acc[i][j] = fmaf(xv[i], wv[j], acc[i][j]);
        }
        __syncthreads();
    }

#pragma unroll
    for (int i = 0; i < 4; i++) {
        int r = row0 + ty4 + i;
        if (r < NN) {
            float4 o1 = make_float4(acc[i][0], acc[i][1], acc[i][2], acc[i][3]);
            float4 o2 = make_float4(acc[i][4], acc[i][5], acc[i][6], acc[i][7]);
            ((float4*)g_H)[r * 32 + tx * 2] = o1;
            ((float4*)g_H)[r * 32 + tx * 2 + 1] = o2;
        }
    }
}

// ---------------- alpha_s / alpha_d: one warp per node ----------------
__global__ void k_alpha(const float* __restrict__ asrc, const float* __restrict__ adst) {
    int g = blockIdx.x * blockDim.x + threadIdx.x;
    int w = g >> 5, lane = g & 31;
    if (w >= NN) return;
    float4 h = ((const float4*)g_H)[w * 32 + lane];
    float4 a = ((const float4*)asrc)[lane];
    float4 b = ((const float4*)adst)[lane];
    float ps = h.x * a.x + h.y * a.y + h.z * a.z + h.w * a.w;
    float pd = h.x * b.x + h.y * b.y + h.z * b.z + h.w * b.w;
    for (int o = 16; o; o >>= 1) {
        ps += __shfl_xor_sync(0xffffffffu, ps, o);
        pd += __shfl_xor_sync(0xffffffffu, pd, o);
    }
    if (lane == 0) { g_as[w] = ps; g_ad[w] = pd; }
}

__device__ __forceinline__ float leaky(float v) { return v > 0.f ? v : 0.2f * v; }
__device__ __forceinline__ float gelu(float v) {
    return 0.5f * v * (1.f + erff(v * 0.70710678118f));
}

// ---------------- aggregation + softmax + bias + gelu: warp per node ----------
// Writes g_ACT directly.
__global__ void k_agg(int layer, const float* __restrict__ biasl) {
    int g = blockIdx.x * blockDim.x + threadIdx.x;
    int n = g >> 5, lane = g & 31;
    if (n >= NN) return;
    int beg = g_rowptr[n], end = g_rowptr[n + 1];
    float ad = g_ad[n];
    float ce = g_ce[layer];

    // pass A: segment max of leaky-relu logits
    float m = -3.0e38f;
    for (int j = beg + lane; j < end; j += 32) {
        float l = leaky(g_as[g_ssrc[j]] + ad + ce * g_sew[j]);
        m = fmaxf(m, l);
    }
    for (int o = 16; o; o >>= 1) m = fmaxf(m, __shfl_xor_sync(0xffffffffu, m, o));

    // pass B: z = sum exp, acc = sum p * h[src] (lane owns cols 4*lane..4*lane+3)
    float z = 0.f;
    float4 acc = make_float4(0.f, 0.f, 0.f, 0.f);
    const float4* Hv = (const float4*)g_H;
    for (int base = beg; base < end; base += 32) {
        int j = base + lane;
        float p = 0.f; int s = 0;
        if (j < end) {
            s = g_ssrc[j];
            float l = leaky(g_as[s] + ad + ce * g_sew[j]);
            p = __expf(l - m);
        }
        z += p;
        int cnt = min(32, end - base);
        // 2-deep pipelined row accumulation (keep next load in flight)
        float pe = __shfl_sync(0xffffffffu, p, 0);
        int   se = __shfl_sync(0xffffffffu, s, 0);
        float4 hv = Hv[se * 32 + lane];
        for (int t = 1; t < cnt; t++) {
            float pen = __shfl_sync(0xffffffffu, p, t);
            int   sen = __shfl_sync(0xffffffffu, s, t);
            float4 nv = Hv[sen * 32 + lane];
            acc.x = fmaf(pe, hv.x, acc.x);
            acc.y = fmaf(pe, hv.y, acc.y);
            acc.z = fmaf(pe, hv.z, acc.z);
            acc.w = fmaf(pe, hv.w, acc.w);
            pe = pen; hv = nv;
        }
        acc.x = fmaf(pe, hv.x, acc.x);
        acc.y = fmaf(pe, hv.y, acc.y);
        acc.z = fmaf(pe, hv.z, acc.z);
        acc.w = fmaf(pe, hv.w, acc.w);
    }
    for (int o = 16; o; o >>= 1) z += __shfl_xor_sync(0xffffffffu, z, o);
    float inv = 1.f / z;
    float4 b = ((const float4*)biasl)[lane];
    float4 o;
    o.x = gelu(acc.x * inv + b.x);
    o.y = gelu(acc.y * inv + b.y);
    o.z = gelu(acc.z * inv + b.z);
    o.w = gelu(acc.w * inv + b.w);
    ((float4*)g_ACT)[n * 32 + lane] = o;
}

// ---------------- residual + layernorm: warp per node ----------------
__global__ void k_ln(const float* __restrict__ x, const float* __restrict__ gam,
                     const float* __restrict__ bet, float* __restrict__ out) {
    int g = blockIdx.x * blockDim.x + threadIdx.x;
    int n = g >> 5, lane = g & 31;
    if (n >= NN) return;
    float4 v = ((const float4*)x)[n * 32 + lane];
    float4 a = ((const float4*)g_ACT)[n * 32 + lane];
    v.x += a.x; v.y += a.y; v.z += a.z; v.w += a.w;
    float s = v.x + v.y + v.z + v.w;
    for (int o = 16; o; o >>= 1) s += __shfl_xor_sync(0xffffffffu, s, o);
    float mu = s * (1.f / 128.f);
    float dx = v.x - mu, dy = v.y - mu, dz = v.z - mu, dw = v.w - mu;
    float q = dx * dx + dy * dy + dz * dz + dw * dw;
    for (int o = 16; o; o >>= 1) q += __shfl_xor_sync(0xffffffffu, q, o);
    float r = rsqrtf(q * (1.f / 128.f) + 1e-5f);
    float4 gg = ((const float4*)gam)[lane];
    float4 bb = ((const float4*)bet)[lane];
    float4 o4;
    o4.x = dx * r * gg.x + bb.x;
    o4.y = dy * r * gg.y + bb.y;
    o4.z = dz * r * gg.z + bb.z;
    o4.w = dw * r * gg.w + bb.w;
    ((float4*)out)[n * 32 + lane] = o4;
}

// ---------------- host: kernel launches ONLY ----------------
extern "C" void kernel_launch(void* const* d_in, const int* in_sizes, int n_in,
                              void* d_out, int out_size) {
    const float* x     = (const float*)d_in[0];
    const int*   ei    = (const int*)d_in[1];     // int32! (JAX x64 disabled)
    const float* ew    = (const float*)d_in[2];
    const float* W     = (const float*)d_in[3];
    const float* asrc  = (const float*)d_in[4];
    const float* adst  = (const float*)d_in[5];
    const float* lew   = (const float*)d_in[6];
    const float* aedge = (const float*)d_in[7];
    const float* bias  = (const float*)d_in[8];
    const float* gam   = (const float*)d_in[9];
    const float* bet   = (const float*)d_in[10];
    float* out = (float*)d_out;
    (void)in_sizes; (void)n_in; (void)out_size;

    const int TB = 256;
    const int gN  = (NN + TB - 1) / TB;
    const int gE  = (EE + TB - 1) / TB;
    const int gM  = (MM + TB - 1) / TB;
    const int gW  = (NN * 32 + TB - 1) / TB;     // one warp per node
    const int nScanBlk = (NN + 1023) / 1024;      // 98
    const int gGemm = (NN + 63) / 64;             // 1563

    // ---- graph preprocessing (CSR with self-loops, mean-fill loop weights) ----
    k_init<<<gN, TB>>>();
    k_deg<<<gE, TB>>>(ei, ew);
    k_loopw<<<gN, TB>>>();
    k_scan1<<<nScanBlk, 1024>>>();
    k_scan2<<<1, 32>>>(nScanBlk);
    k_scan3<<<gN, TB>>>();
    k_scatter<<<gM, TB>>>(ei, ew);
    k_ce<<<1, 128>>>(lew, aedge);

    // ---- layer 0 ----
    k_gemm<0><<<gGemm, TB>>>(x, W);
    k_alpha<<<gW, TB>>>(asrc, adst);
    k_agg<<<gW, TB>>>(0, bias);

    // ---- layer 1 ----
    k_gemm<1><<<gGemm, TB>>>(nullptr, W + DD * DD);
    k_alpha<<<gW, TB>>>(asrc + DD, adst + DD);
    k_agg<<<gW, TB>>>(1, bias + DD);

    // ---- residual + layernorm ----
    k_ln<<<gW, TB>>>(x, gam, bet, out);
}

// round 7
// speedup vs baseline: 1.9576x; 1.9576x over previous
#include <cuda_runtime.h>
#include <math.h>

#define NN 100000
#define EE 1600000
#define MM (EE + NN)
#define DD 128

// ---------------- scratch (static device allocations; no runtime alloc) ----
__device__ int   g_deg[NN];
__device__ float g_sumw[NN];
__device__ float g_loopw[NN];
__device__ int   g_rowptr[NN + 1];
__device__ int   g_wp[NN];
__device__ int   g_bsum[128];
__device__ int   g_ssrc[MM];
__device__ float g_sew[MM];
__device__ float g_as[NN];
__device__ float g_ad[NN];
__device__ __align__(16) float g_H[(size_t)NN * DD];
__device__ __align__(16) float g_ACT[(size_t)NN * DD];
__device__ float g_ce[2];

// ---------------- preprocessing ----------------
__global__ void k_init() {
    int i = blockIdx.x * blockDim.x + threadIdx.x;
    if (i < NN) { g_deg[i] = 0; g_sumw[i] = 0.f; }
}

// edge_index is int32
__global__ void k_deg(const int* __restrict__ ei, const float* __restrict__ ew) {
    int i = blockIdx.x * blockDim.x + threadIdx.x;
    if (i < EE) {
        int d = ei[EE + i];
        atomicAdd(&g_deg[d], 1);
        atomicAdd(&g_sumw[d], ew[i]);
    }
}

__global__ void k_scan1() {
    __shared__ int s[1024];
    int i = blockIdx.x * 1024 + threadIdx.x;
    int v = (i < NN) ? g_deg[i] + 1 : 0;   // +1 self-loop
    s[threadIdx.x] = v;
    __syncthreads();
    for (int off = 1; off < 1024; off <<= 1) {
        int t = (threadIdx.x >= off) ? s[threadIdx.x - off] : 0;
        __syncthreads();
        s[threadIdx.x] += t;
        __syncthreads();
    }
    if (i < NN) g_rowptr[i] = s[threadIdx.x] - v;   // exclusive within block
    if (threadIdx.x == 1023) g_bsum[blockIdx.x] = s[1023];
}

// block-sum serial scan (thread 0) + c_e = lew . att_edge (all 128 threads)
__global__ void k_scan2ce(int nb, const float* __restrict__ lew, const float* __restrict__ ae) {
    int t = threadIdx.x;   // 128 threads
    float p0 = lew[t] * ae[t];
    float p1 = lew[DD + t] * ae[DD + t];
    for (int o = 16; o; o >>= 1) {
        p0 += __shfl_xor_sync(0xffffffffu, p0, o);
        p1 += __shfl_xor_sync(0xffffffffu, p1, o);
    }
    __shared__ float s0[4], s1[4];
    if ((t & 31) == 0) { s0[t >> 5] = p0; s1[t >> 5] = p1; }
    __syncthreads();
    if (t == 0) {
        g_ce[0] = s0[0] + s0[1] + s0[2] + s0[3];
        g_ce[1] = s1[0] + s1[1] + s1[2] + s1[3];
        int acc = 0;
        for (int b = 0; b < nb; b++) { int x = g_bsum[b]; g_bsum[b] = acc; acc += x; }
        g_rowptr[NN] = MM;
    }
}

// finalize rowptr + loop weights
__global__ void k_scan3() {
    int i = blockIdx.x * blockDim.x + threadIdx.x;
    if (i < NN) {
        int v = g_rowptr[i] + g_bsum[i >> 10];
        g_rowptr[i] = v;
        g_wp[i] = v;
        int d = g_deg[i];
        g_loopw[i] = g_sumw[i] / (float)(d > 1 ? d : 1);
    }
}

__global__ void k_scatter(const int* __restrict__ ei, const float* __restrict__ ew) {
    int i = blockIdx.x * blockDim.x + threadIdx.x;
    if (i < EE) {
        int s = ei[i];
        int d = ei[EE + i];
        int pos = atomicAdd(&g_wp[d], 1);
        g_ssrc[pos] = s;
        g_sew[pos] = ew[i];
    } else if (i < MM) {
        int n = i - EE;
        int pos = atomicAdd(&g_wp[n], 1);
        g_ssrc[pos] = n;
        g_sew[pos] = g_loopw[n];
    }
}

// ---------------- GEMM 128x128 tile / block, 8x8 per thread, fused alpha ----
// 256 threads: tx=tid&15 -> cols tx*8..+7, ty=tid>>4 -> rows ty*8..+7.
// X smem stored transposed (sXT[k][row]) so xv loads are LDS.128 broadcasts.
// Epilogue computes alpha_s/alpha_d (h . att vectors) via 16-lane shfl reduce.
// SRC=0: read Xin; SRC=1: read g_ACT. Writes g_H, g_as, g_ad.
template<int SRC>
__global__ void __launch_bounds__(256, 2)
k_gemm(const float* __restrict__ Xin, const float* __restrict__ Wg,
       const float* __restrict__ asrc, const float* __restrict__ adst) {
    __shared__ __align__(16) float sW[32][DD];     // 16 KB
    __shared__ __align__(16) float sXT[32][132];   // 16.9 KB, transposed, pad 132
    const float* __restrict__ X = (SRC == 0) ? Xin : (const float*)g_ACT;

    int tid = threadIdx.x;
    int row0 = blockIdx.x * 128;
    int tx = tid & 15, ty = tid >> 4;
    int ty8 = ty * 8, c0 = tx * 8;

    float acc[8][8];
#pragma unroll
    for (int i = 0; i < 8; i++)
#pragma unroll
        for (int j = 0; j < 8; j++) acc[i][j] = 0.f;

    for (int kc = 0; kc < DD; kc += 32) {
        // W chunk [32][128]: 1024 float4, 4/thread
#pragma unroll
        for (int t = 0; t < 4; t++) {
            int idx = tid + t * 256;
            int r = idx >> 5, c4 = idx & 31;
            *(float4*)&sW[r][c4 * 4] = ((const float4*)Wg)[(kc + r) * 32 + c4];
        }
        // X chunk [128 rows][32 k] -> transposed scatter: 1024 float4, 4/thread
#pragma unroll
        for (int t = 0; t < 4; t++) {
            int idx = tid + t * 256;
            int r = idx >> 3, c4 = idx & 7;
            float4 v = make_float4(0.f, 0.f, 0.f, 0.f);
            int gr = row0 + r;
            if (gr < NN) v = ((const float4*)X)[gr * 32 + (kc >> 2) + c4];
            sXT[c4 * 4 + 0][r] = v.x;
            sXT[c4 * 4 + 1][r] = v.y;
            sXT[c4 * 4 + 2][r] = v.z;
            sXT[c4 * 4 + 3][r] = v.w;
        }
        __syncthreads();

#pragma unroll
        for (int kk = 0; kk < 32; kk++) {
            float4 wa = *(const float4*)&sW[kk][c0];
            float4 wb = *(const float4*)&sW[kk][c0 + 4];
            float4 xa = *(const float4*)&sXT[kk][ty8];
            float4 xb = *(const float4*)&sXT[kk][ty8 + 4];
            float wv[8] = {wa.x, wa.y, wa.z, wa.w, wb.x, wb.y, wb.z, wb.w};
            float xv[8] = {xa.x, xa.y, xa.z, xa.w, xb.x, xb.y, xb.z, xb.w};
#pragma unroll
            for (int i = 0; i < 8; i++)
#pragma unroll
                for (int j = 0; j < 8; j++)
                    acc[i][j] = fmaf(xv[i], wv[j], acc[i][j]);
        }
        __syncthreads();
    }

    // store H + fused alpha
    float4 a0 = ((const float4*)asrc)[tx * 2];
    float4 a1 = ((const float4*)asrc)[tx * 2 + 1];
    float4 b0 = ((const float4*)adst)[tx * 2];
    float4 b1 = ((const float4*)adst)[tx * 2 + 1];
#pragma unroll
    for (int i = 0; i < 8; i++) {
        int r = row0 + ty8 + i;
        bool ok = (r < NN);
        if (ok) {
            float4 o1 = make_float4(acc[i][0], acc[i][1], acc[i][2], acc[i][3]);
            float4 o2 = make_float4(acc[i][4], acc[i][5], acc[i][6], acc[i][7]);
            ((float4*)g_H)[r * 32 + tx * 2] = o1;
            ((float4*)g_H)[r * 32 + tx * 2 + 1] = o2;
        }
        float ps = acc[i][0] * a0.x + acc[i][1] * a0.y + acc[i][2] * a0.z + acc[i][3] * a0.w
                 + acc[i][4] * a1.x + acc[i][5] * a1.y + acc[i][6] * a1.z + acc[i][7] * a1.w;
        float pd = acc[i][0] * b0.x + acc[i][1] * b0.y + acc[i][2] * b0.z + acc[i][3] * b0.w
                 + acc[i][4] * b1.x + acc[i][5] * b1.y + acc[i][6] * b1.z + acc[i][7] * b1.w;
#pragma unroll
        for (int o = 8; o; o >>= 1) {
            ps += __shfl_xor_sync(0xffffffffu, ps, o);
            pd += __shfl_xor_sync(0xffffffffu, pd, o);
        }
        if (tx == 0 && ok) { g_as[r] = ps; g_ad[r] = pd; }
    }
}

__device__ __forceinline__ float leaky(float v) { return v > 0.f ? v : 0.2f * v; }
__device__ __forceinline__ float gelu(float v) {
    return 0.5f * v * (1.f + erff(v * 0.70710678118f));
}

// ---------------- aggregation + softmax + bias + gelu (+residual/LN): warp/node
// FUSE_LN=0: writes g_ACT. FUSE_LN=1: out = LN(x + gelu_row).
template<int FUSE_LN>
__global__ void k_agg(int layer, const float* __restrict__ biasl,
                      const float* __restrict__ x, const float* __restrict__ gam,
                      const float* __restrict__ bet, float* __restrict__ outp) {
    int g = blockIdx.x * blockDim.x + threadIdx.x;
    int n = g >> 5, lane = g & 31;
    if (n >= NN) return;
    int beg = g_rowptr[n], end = g_rowptr[n + 1];
    float ad = g_ad[n];
    float ce = g_ce[layer];

    // pass A: segment max of leaky-relu logits
    float m = -3.0e38f;
    for (int j = beg + lane; j < end; j += 32) {
        float l = leaky(g_as[g_ssrc[j]] + ad + ce * g_sew[j]);
        m = fmaxf(m, l);
    }
    for (int o = 16; o; o >>= 1) m = fmaxf(m, __shfl_xor_sync(0xffffffffu, m, o));

    // pass B: z = sum exp, acc = sum p * h[src] (lane owns cols 4*lane..4*lane+3)
    float z = 0.f;
    float4 acc = make_float4(0.f, 0.f, 0.f, 0.f);
    const float4* Hv = (const float4*)g_H;
    for (int base = beg; base < end; base += 32) {
        int j = base + lane;
        float p = 0.f; int s = 0;
        if (j < end) {
            s = g_ssrc[j];
            float l = leaky(g_as[s] + ad + ce * g_sew[j]);
            p = __expf(l - m);
        }
        z += p;
        int cnt = min(32, end - base);
        float pe = __shfl_sync(0xffffffffu, p, 0);
        int   se = __shfl_sync(0xffffffffu, s, 0);
        float4 hv = Hv[se * 32 + lane];
        for (int t = 1; t < cnt; t++) {
            float pen = __shfl_sync(0xffffffffu, p, t);
            int   sen = __shfl_sync(0xffffffffu, s, t);
            float4 nv = Hv[sen * 32 + lane];
            acc.x = fmaf(pe, hv.x, acc.x);
            acc.y = fmaf(pe, hv.y, acc.y);
            acc.z = fmaf(pe, hv.z, acc.z);
            acc.w = fmaf(pe, hv.w, acc.w);
            pe = pen; hv = nv;
        }
        acc.x = fmaf(pe, hv.x, acc.x);
        acc.y = fmaf(pe, hv.y, acc.y);
        acc.z = fmaf(pe, hv.z, acc.z);
        acc.w = fmaf(pe, hv.w, acc.w);
    }
    for (int o = 16; o; o >>= 1) z += __shfl_xor_sync(0xffffffffu, z, o);
    float inv = 1.f / z;
    float4 b = ((const float4*)biasl)[lane];
    float4 o;
    o.x = gelu(acc.x * inv + b.x);
    o.y = gelu(acc.y * inv + b.y);
    o.z = gelu(acc.z * inv + b.z);
    o.w = gelu(acc.w * inv + b.w);

    if (FUSE_LN == 0) {
        ((float4*)g_ACT)[n * 32 + lane] = o;
    } else {
        float4 v = ((const float4*)x)[n * 32 + lane];
        v.x += o.x; v.y += o.y; v.z += o.z; v.w += o.w;
        float s = v.x + v.y + v.z + v.w;
        for (int oo = 16; oo; oo >>= 1) s += __shfl_xor_sync(0xffffffffu, s, oo);
        float mu = s * (1.f / 128.f);
        float dx = v.x - mu, dy = v.y - mu, dz = v.z - mu, dw = v.w - mu;
        float q = dx * dx + dy * dy + dz * dz + dw * dw;
        for (int oo = 16; oo; oo >>= 1) q += __shfl_xor_sync(0xffffffffu, q, oo);
        float r = rsqrtf(q * (1.f / 128.f) + 1e-5f);
        float4 gg = ((const float4*)gam)[lane];
        float4 bb = ((const float4*)bet)[lane];
        float4 o4;
        o4.x = dx * r * gg.x + bb.x;
        o4.y = dy * r * gg.y + bb.y;
        o4.z = dz * r * gg.z + bb.z;
        o4.w = dw * r * gg.w + bb.w;
        ((float4*)outp)[n * 32 + lane] = o4;
    }
}

// ---------------- host: kernel launches ONLY ----------------
extern "C" void kernel_launch(void* const* d_in, const int* in_sizes, int n_in,
                              void* d_out, int out_size) {
    const float* x     = (const float*)d_in[0];
    const int*   ei    = (const int*)d_in[1];     // int32
    const float* ew    = (const float*)d_in[2];
    const float* W     = (const float*)d_in[3];
    const float* asrc  = (const float*)d_in[4];
    const float* adst  = (const float*)d_in[5];
    const float* lew   = (const float*)d_in[6];
    const float* aedge = (const float*)d_in[7];
    const float* bias  = (const float*)d_in[8];
    const float* gam   = (const float*)d_in[9];
    const float* bet   = (const float*)d_in[10];
    float* out = (float*)d_out;
    (void)in_sizes; (void)n_in; (void)out_size;

    const int TB = 256;
    const int gN  = (NN + TB - 1) / TB;
    const int gE  = (EE + TB - 1) / TB;
    const int gM  = (MM + TB - 1) / TB;
    const int gW  = (NN * 32 + TB - 1) / TB;      // one warp per node
    const int nScanBlk = (NN + 1023) / 1024;       // 98
    const int gGemm = (NN + 127) / 128;            // 782

    // ---- graph preprocessing (CSR with self-loops, mean-fill loop weights) ----
    k_init<<<gN, TB>>>();
    k_deg<<<gE, TB>>>(ei, ew);
    k_scan1<<<nScanBlk, 1024>>>();
    k_scan2ce<<<1, 128>>>(nScanBlk, lew, aedge);
    k_scan3<<<gN, TB>>>();
    k_scatter<<<gM, TB>>>(ei, ew);

    // ---- layer 0 ----
    k_gemm<0><<<gGemm, TB>>>(x, W, asrc, adst);
    k_agg<0><<<gW, TB>>>(0, bias, nullptr, nullptr, nullptr, nullptr);

    // ---- layer 1 (agg fuses residual + layernorm) ----
    k_gemm<1><<<gGemm, TB>>>(nullptr, W + DD * DD, asrc + DD, adst + DD);
    k_agg<1><<<gW, TB>>>(1, bias + DD, x, gam, bet, out);
}

// round 8
// speedup vs baseline: 2.0491x; 1.0468x over previous
#include <cuda_runtime.h>
#include <math.h>

#define NN 100000
#define EE 1600000
#define MM (EE + NN)
#define DD 128

struct __align__(8) Edge { int s; float w; };

// ---------------- scratch (static device allocations; no runtime alloc) ----
__device__ int   g_deg[NN];
__device__ float g_sumw[NN];
__device__ float g_loopw[NN];
__device__ int   g_rowptr[NN + 1];
__device__ int   g_wp[NN];
__device__ int   g_bsum[128];
__device__ Edge  g_edge[MM];
__device__ float g_as[NN];
__device__ float g_ad[NN];
__device__ __align__(16) float g_H[(size_t)NN * DD];
__device__ __align__(16) float g_ACT[(size_t)NN * DD];
__device__ float g_ce[2];

// ---------------- preprocessing ----------------
__global__ void k_init() {
    int i = blockIdx.x * blockDim.x + threadIdx.x;
    if (i < NN) { g_deg[i] = 0; g_sumw[i] = 0.f; }
}

// edge_index is int32
__global__ void k_deg(const int* __restrict__ ei, const float* __restrict__ ew) {
    int i = blockIdx.x * blockDim.x + threadIdx.x;
    if (i < EE) {
        int d = ei[EE + i];
        atomicAdd(&g_deg[d], 1);
        atomicAdd(&g_sumw[d], ew[i]);
    }
}

__global__ void k_scan1() {
    __shared__ int s[1024];
    int i = blockIdx.x * 1024 + threadIdx.x;
    int v = (i < NN) ? g_deg[i] + 1 : 0;   // +1 self-loop
    s[threadIdx.x] = v;
    __syncthreads();
    for (int off = 1; off < 1024; off <<= 1) {
        int t = (threadIdx.x >= off) ? s[threadIdx.x - off] : 0;
        __syncthreads();
        s[threadIdx.x] += t;
        __syncthreads();
    }
    if (i < NN) g_rowptr[i] = s[threadIdx.x] - v;   // exclusive within block
    if (threadIdx.x == 1023) g_bsum[blockIdx.x] = s[1023];
}

// parallel block-sum scan (128 elems) + c_e = lew . att_edge
__global__ void k_scan2ce(int nb, const float* __restrict__ lew, const float* __restrict__ ae) {
    __shared__ int sc[128];
    int t = threadIdx.x;   // 128 threads
    float p0 = lew[t] * ae[t];
    float p1 = lew[DD + t] * ae[DD + t];
    for (int o = 16; o; o >>= 1) {
        p0 += __shfl_xor_sync(0xffffffffu, p0, o);
        p1 += __shfl_xor_sync(0xffffffffu, p1, o);
    }
    __shared__ float s0[4], s1[4];
    if ((t & 31) == 0) { s0[t >> 5] = p0; s1[t >> 5] = p1; }

    int v = (t < nb) ? g_bsum[t] : 0;
    sc[t] = v;
    __syncthreads();
    for (int off = 1; off < 128; off <<= 1) {
        int a = (t >= off) ? sc[t - off] : 0;
        __syncthreads();
        sc[t] += a;
        __syncthreads();
    }
    if (t < nb) g_bsum[t] = sc[t] - v;   // exclusive
    if (t == 0) {
        g_ce[0] = s0[0] + s0[1] + s0[2] + s0[3];
        g_ce[1] = s1[0] + s1[1] + s1[2] + s1[3];
        g_rowptr[NN] = MM;
    }
}

// finalize rowptr + loop weights
__global__ void k_scan3() {
    int i = blockIdx.x * blockDim.x + threadIdx.x;
    if (i < NN) {
        int v = g_rowptr[i] + g_bsum[i >> 10];
        g_rowptr[i] = v;
        g_wp[i] = v;
        int d = g_deg[i];
        g_loopw[i] = g_sumw[i] / (float)(d > 1 ? d : 1);
    }
}

__global__ void k_scatter(const int* __restrict__ ei, const float* __restrict__ ew) {
    int i = blockIdx.x * blockDim.x + threadIdx.x;
    if (i < EE) {
        int s = ei[i];
        int d = ei[EE + i];
        int pos = atomicAdd(&g_wp[d], 1);
        Edge e; e.s = s; e.w = ew[i];
        g_edge[pos] = e;
    } else if (i < MM) {
        int n = i - EE;
        int pos = atomicAdd(&g_wp[n], 1);
        Edge e; e.s = n; e.w = g_loopw[n];
        g_edge[pos] = e;
    }
}

// ---------------- GEMM 128x128 tile / block, 8x8 per thread, fused alpha ----
template<int SRC>
__global__ void __launch_bounds__(256, 2)
k_gemm(const float* __restrict__ Xin, const float* __restrict__ Wg,
       const float* __restrict__ asrc, const float* __restrict__ adst) {
    __shared__ __align__(16) float sW[32][DD];     // 16 KB
    __shared__ __align__(16) float sXT[32][132];   // 16.9 KB, transposed, pad 132
    const float* __restrict__ X = (SRC == 0) ? Xin : (const float*)g_ACT;

    int tid = threadIdx.x;
    int row0 = blockIdx.x * 128;
    int tx = tid & 15, ty = tid >> 4;
    int ty8 = ty * 8, c0 = tx * 8;

    float acc[8][8];
#pragma unroll
    for (int i = 0; i < 8; i++)
#pragma unroll
        for (int j = 0; j < 8; j++) acc[i][j] = 0.f;

    for (int kc = 0; kc < DD; kc += 32) {
#pragma unroll
        for (int t = 0; t < 4; t++) {
            int idx = tid + t * 256;
            int r = idx >> 5, c4 = idx & 31;
            *(float4*)&sW[r][c4 * 4] = ((const float4*)Wg)[(kc + r) * 32 + c4];
        }
#pragma unroll
        for (int t = 0; t < 4; t++) {
            int idx = tid + t * 256;
            int r = idx >> 3, c4 = idx & 7;
            float4 v = make_float4(0.f, 0.f, 0.f, 0.f);
            int gr = row0 + r;
            if (gr < NN) v = ((const float4*)X)[gr * 32 + (kc >> 2) + c4];
            sXT[c4 * 4 + 0][r] = v.x;
            sXT[c4 * 4 + 1][r] = v.y;
            sXT[c4 * 4 + 2][r] = v.z;
            sXT[c4 * 4 + 3][r] = v.w;
        }
        __syncthreads();

#pragma unroll
        for (int kk = 0; kk < 32; kk++) {
            float4 wa = *(const float4*)&sW[kk][c0];
            float4 wb = *(const float4*)&sW[kk][c0 + 4];
            float4 xa = *(const float4*)&sXT[kk][ty8];
            float4 xb = *(const float4*)&sXT[kk][ty8 + 4];
            float wv[8] = {wa.x, wa.y, wa.z, wa.w, wb.x, wb.y, wb.z, wb.w};
            float xv[8] = {xa.x, xa.y, xa.z, xa.w, xb.x, xb.y, xb.z, xb.w};
#pragma unroll
            for (int i = 0; i < 8; i++)
#pragma unroll
                for (int j = 0; j < 8; j++)
                    acc[i][j] = fmaf(xv[i], wv[j], acc[i][j]);
        }
        __syncthreads();
    }

    // store H + fused alpha
    float4 a0 = ((const float4*)asrc)[tx * 2];
    float4 a1 = ((const float4*)asrc)[tx * 2 + 1];
    float4 b0 = ((const float4*)adst)[tx * 2];
    float4 b1 = ((const float4*)adst)[tx * 2 + 1];
#pragma unroll
    for (int i = 0; i < 8; i++) {
        int r = row0 + ty8 + i;
        bool ok = (r < NN);
        if (ok) {
            float4 o1 = make_float4(acc[i][0], acc[i][1], acc[i][2], acc[i][3]);
            float4 o2 = make_float4(acc[i][4], acc[i][5], acc[i][6], acc[i][7]);
            ((float4*)g_H)[r * 32 + tx * 2] = o1;
            ((float4*)g_H)[r * 32 + tx * 2 + 1] = o2;
        }
        float ps = acc[i][0] * a0.x + acc[i][1] * a0.y + acc[i][2] * a0.z + acc[i][3] * a0.w
                 + acc[i][4] * a1.x + acc[i][5] * a1.y + acc[i][6] * a1.z + acc[i][7] * a1.w;
        float pd = acc[i][0] * b0.x + acc[i][1] * b0.y + acc[i][2] * b0.z + acc[i][3] * b0.w
                 + acc[i][4] * b1.x + acc[i][5] * b1.y + acc[i][6] * b1.z + acc[i][7] * b1.w;
#pragma unroll
        for (int o = 8; o; o >>= 1) {
            ps += __shfl_xor_sync(0xffffffffu, ps, o);
            pd += __shfl_xor_sync(0xffffffffu, pd, o);
        }
        if (tx == 0 && ok) { g_as[r] = ps; g_ad[r] = pd; }
    }
}

__device__ __forceinline__ float leaky(float v) { return v > 0.f ? v : 0.2f * v; }
__device__ __forceinline__ float gelu(float v) {
    return 0.5f * v * (1.f + erff(v * 0.70710678118f));
}

// ---------------- single-pass online-softmax aggregation: warp per node -----
// FUSE_LN=0: writes g_ACT. FUSE_LN=1: out = LN(x + gelu_row).
template<int FUSE_LN>
__global__ void k_agg(int layer, const float* __restrict__ biasl,
                      const float* __restrict__ x, const float* __restrict__ gam,
                      const float* __restrict__ bet, float* __restrict__ outp) {
    int g = blockIdx.x * blockDim.x + threadIdx.x;
    int n = g >> 5, lane = g & 31;
    if (n >= NN) return;
    int beg = g_rowptr[n], end = g_rowptr[n + 1];
    float ad = g_ad[n];
    float ce = g_ce[layer];

    float m = -3.0e38f, z = 0.f;
    float4 acc = make_float4(0.f, 0.f, 0.f, 0.f);
    const float4* Hv = (const float4*)g_H;

    for (int base = beg; base < end; base += 32) {
        int j = base + lane;
        float l = -3.0e38f; int s = 0;
        if (j < end) {
            Edge e = g_edge[j];
            s = e.s;
            l = leaky(g_as[s] + ad + ce * e.w);
        }
        // batch max + online rescale
        float bm = l;
#pragma unroll
        for (int o = 16; o; o >>= 1) bm = fmaxf(bm, __shfl_xor_sync(0xffffffffu, bm, o));
        float mn = fmaxf(m, bm);
        float scale = __expf(m - mn);       // first batch: exp(-huge) = 0
        z *= scale;
        acc.x *= scale; acc.y *= scale; acc.z *= scale; acc.w *= scale;
        m = mn;
        float p = (j < end) ? __expf(l - m) : 0.f;
        z += p;

        int cnt = min(32, end - base);
        // 2-deep pipelined row accumulation
        float pe = __shfl_sync(0xffffffffu, p, 0);
        int   se = __shfl_sync(0xffffffffu, s, 0);
        float4 hv = Hv[se * 32 + lane];
        for (int t = 1; t < cnt; t++) {
            float pen = __shfl_sync(0xffffffffu, p, t);
            int   sen = __shfl_sync(0xffffffffu, s, t);
            float4 nv = Hv[sen * 32 + lane];
            acc.x = fmaf(pe, hv.x, acc.x);
            acc.y = fmaf(pe, hv.y, acc.y);
            acc.z = fmaf(pe, hv.z, acc.z);
            acc.w = fmaf(pe, hv.w, acc.w);
            pe = pen; hv = nv;
        }
        acc.x = fmaf(pe, hv.x, acc.x);
        acc.y = fmaf(pe, hv.y, acc.y);
        acc.z = fmaf(pe, hv.z, acc.z);
        acc.w = fmaf(pe, hv.w, acc.w);
    }
#pragma unroll
    for (int o = 16; o; o >>= 1) z += __shfl_xor_sync(0xffffffffu, z, o);
    float inv = 1.f / z;
    float4 b = ((const float4*)biasl)[lane];
    float4 o;
    o.x = gelu(acc.x * inv + b.x);
    o.y = gelu(acc.y * inv + b.y);
    o.z = gelu(acc.z * inv + b.z);
    o.w = gelu(acc.w * inv + b.w);

    if (FUSE_LN == 0) {
        ((float4*)g_ACT)[n * 32 + lane] = o;
    } else {
        float4 v = ((const float4*)x)[n * 32 + lane];
        v.x += o.x; v.y += o.y; v.z += o.z; v.w += o.w;
        float s = v.x + v.y + v.z + v.w;
#pragma unroll
        for (int oo = 16; oo; oo >>= 1) s += __shfl_xor_sync(0xffffffffu, s, oo);
        float mu = s * (1.f / 128.f);
        float dx = v.x - mu, dy = v.y - mu, dz = v.z - mu, dw = v.w - mu;
        float q = dx * dx + dy * dy + dz * dz + dw * dw;
#pragma unroll
        for (int oo = 16; oo; oo >>= 1) q += __shfl_xor_sync(0xffffffffu, q, oo);
        float r = rsqrtf(q * (1.f / 128.f) + 1e-5f);
        float4 gg = ((const float4*)gam)[lane];
        float4 bb = ((const float4*)bet)[lane];
        float4 o4;
        o4.x = dx * r * gg.x + bb.x;
        o4.y = dy * r * gg.y + bb.y;
        o4.z = dz * r * gg.z + bb.z;
        o4.w = dw * r * gg.w + bb.w;
        ((float4*)outp)[n * 32 + lane] = o4;
    }
}

// ---------------- host: kernel launches ONLY ----------------
extern "C" void kernel_launch(void* const* d_in, const int* in_sizes, int n_in,
                              void* d_out, int out_size) {
    const float* x     = (const float*)d_in[0];
    const int*   ei    = (const int*)d_in[1];     // int32
    const float* ew    = (const float*)d_in[2];
    const float* W     = (const float*)d_in[3];
    const float* asrc  = (const float*)d_in[4];
    const float* adst  = (const float*)d_in[5];
    const float* lew   = (const float*)d_in[6];
    const float* aedge = (const float*)d_in[7];
    const float* bias  = (const float*)d_in[8];
    const float* gam   = (const float*)d_in[9];
    const float* bet   = (const float*)d_in[10];
    float* out = (float*)d_out;
    (void)in_sizes; (void)n_in; (void)out_size;

    const int TB = 256;
    const int gN  = (NN + TB - 1) / TB;
    const int gE  = (EE + TB - 1) / TB;
    const int gM  = (MM + TB - 1) / TB;
    const int gW  = (NN * 32 + TB - 1) / TB;      // one warp per node
    const int nScanBlk = (NN + 1023) / 1024;       // 98
    const int gGemm = (NN + 127) / 128;            // 782

    // ---- graph preprocessing (CSR with self-loops, mean-fill loop weights) ----
    k_init<<<gN, TB>>>();
    k_deg<<<gE, TB>>>(ei, ew);
    k_scan1<<<nScanBlk, 1024>>>();
    k_scan2ce<<<1, 128>>>(nScanBlk, lew, aedge);
    k_scan3<<<gN, TB>>>();
    k_scatter<<<gM, TB>>>(ei, ew);

    // ---- layer 0 ----
    k_gemm<0><<<gGemm, TB>>>(x, W, asrc, adst);
    k_agg<0><<<gW, TB>>>(0, bias, nullptr, nullptr, nullptr, nullptr);

    // ---- layer 1 (agg fuses residual + layernorm) ----
    k_gemm<1><<<gGemm, TB>>>(nullptr, W + DD * DD, asrc + DD, adst + DD);
    k_agg<1><<<gW, TB>>>(1, bias + DD, x, gam, bet, out);
}